// round 11
// baseline (speedup 1.0000x reference)
#include <cuda_runtime.h>
#include <math.h>

#define Lc 8
#define Pc 8
#define Sc 128
#define Bc 16
#define Wc 768
#define Mc 64
#define W4   (Wc / 4)            // 192 float4 per W row == NTHR
#define ROW4 ((Bc * Wc) / 4)     // s-stride in float4 = 3072
#define NTHR 192
#define CK   12                  // float4 per epilogue w-chunk
#define NCHK (W4 / CK)           // 16 chunks -> 256 epilogue CTAs

// Scratch (allocation-free: __device__ globals, zero-initialized at load)
// g_sem is ACCUMULATED by k1 (atomicAdd) and ZEROED by its unique reader in
// k_epi right after consumption -> invariant "g_sem == 0 at k1 entry" holds
// for the correctness call and every graph replay alike.
__device__ float g_sem[Lc * Bc * Wc];       // [l,b,w] unnormalized sem (384 KB)
__device__ float g_e[Lc * Pc * Bc];         // e_p = exp(sigmoid(score)) per (l,p,b)

// ---------------------------------------------------------------------------
// Kernel 1: streaming pass. 1024 blocks x 192 threads; thread t owns float4
// column t, walks 128 s-rows. After the block reduce it computes its own
// e = exp(sigmoid(score+bias)) and atomically accumulates e*max into g_sem.
// NO g_mp: the 3 MB DRAM round-trip is gone.
// ---------------------------------------------------------------------------
__global__ __launch_bounds__(NTHR, 8)
void k1_pass(const float* __restrict__ embeds,
             const float* __restrict__ w0,
             const float* __restrict__ w1,
             const float* __restrict__ b0,
             const float* __restrict__ b1)
{
    __shared__ float sw1[Sc];
    __shared__ float sred[6];
    __shared__ float s_e;

    const int t = threadIdx.x;             // 0..191
    if (t < Sc) sw1[t] = __ldg(w1 + t);
    __syncthreads();

    const int lpb = blockIdx.x;            // (l*P + p)*B + b
    const int b   = lpb & (Bc - 1);
    const int lp  = lpb >> 4;              // l*8 + p
    const int l   = lp >> 3;

    const float4* base = reinterpret_cast<const float4*>(embeds)
                       + (size_t)lp * Sc * ROW4 + (size_t)b * W4 + t;
    const float4 w0v = __ldg(reinterpret_cast<const float4*>(w0) + t);

    float4 mx = make_float4(-3.4e38f, -3.4e38f, -3.4e38f, -3.4e38f);
    float dot = 0.0f;

    #pragma unroll 4
    for (int s = 0; s < Sc; s++) {
        float4 v = __ldcs(base + (size_t)s * ROW4);   // streaming (evict-first)
        mx.x = fmaxf(mx.x, v.x);
        mx.y = fmaxf(mx.y, v.y);
        mx.z = fmaxf(mx.z, v.z);
        mx.w = fmaxf(mx.w, v.w);
        dot += (v.x * w0v.x + v.y * w0v.y + v.z * w0v.z + v.w * w0v.w) * sw1[s];
    }

    // block-reduce dot
    #pragma unroll
    for (int o = 16; o > 0; o >>= 1)
        dot += __shfl_down_sync(0xffffffffu, dot, o);
    if ((t & 31) == 0) sred[t >> 5] = dot;
    __syncthreads();
    if (t == 0) {
        float score = sred[0] + sred[1] + sred[2] + sred[3] + sred[4] + sred[5];
        float sw = 0.0f;
        #pragma unroll 8
        for (int i = 0; i < Sc; i++) sw += sw1[i];
        score += b0[0] * sw + b1[0];                      // + bias
        float sig = 1.0f / (1.0f + __expf(-score));       // sigmoid in (0,1)
        float e   = __expf(sig);                          // unnormalized softmax wt
        g_e[lpb] = e;                                     // plain store (overwritten)
        s_e = e;
    }
    __syncthreads();

    // accumulate e * max into sem[l,b,w] (4 coalesced REDG.F32 per thread)
    const float e = s_e;
    float* semp = g_sem + ((size_t)l * Bc + b) * Wc + 4 * t;
    atomicAdd(semp + 0, e * mx.x);
    atomicAdd(semp + 1, e * mx.y);
    atomicAdd(semp + 2, e * mx.z);
    atomicAdd(semp + 3, e * mx.w);
}

// ---------------------------------------------------------------------------
// Kernel 2: epilogue. 256 CTAs = (b, w-chunk of 12 float4).
//   s_e     <- g_e[.,.,b]  (64 values)
//   s_sem   <- g_sem[l,b,wchunk] * (1/sum_p e)   ... then ZERO g_sem cell
//   out     <- 64 m x 12 float4 (192 threads x 4, smem FMAs)
// Each g_sem cell has exactly one reader (partitioned by (l,b,w)) -> the
// read-then-zero is race-free and restores the k1 entry invariant.
// ---------------------------------------------------------------------------
__global__ __launch_bounds__(NTHR)
void k_epi(const float* __restrict__ mask,
           float* __restrict__ out)
{
    __shared__ float  s_mask[Lc * Mc];       // 512 floats = mask[b,:,:]
    __shared__ float  s_e[Lc * Pc];
    __shared__ float4 s_sem[Lc][CK];

    const int t     = threadIdx.x;           // 0..191
    const int b     = blockIdx.x >> 4;
    const int chunk = blockIdx.x & (NCHK - 1);
    const int wbase = chunk * CK;             // float4 offset within W4

    // e values first (needed by the sem stage)
    if (t < Lc * Pc)
        s_e[t] = __ldcg(g_e + t * Bc + b);
    // mask[b,:,:] -> smem
    #pragma unroll
    for (int i = t; i < Lc * Mc; i += NTHR)
        s_mask[i] = __ldg(mask + (size_t)b * Lc * Mc + i);
    __syncthreads();

    // normalize sem chunk, then zero the global cell (sole reader)
    if (t < Lc * CK) {
        const int l = t / CK;
        const int k = t % CK;
        float inv = 0.0f;
        #pragma unroll
        for (int p = 0; p < Pc; p++) inv += s_e[l * Pc + p];
        inv = 1.0f / inv;

        float4* cell = reinterpret_cast<float4*>(
            g_sem + ((size_t)l * Bc + b) * Wc) + wbase + k;
        float4 v = __ldcg(cell);
        s_sem[l][k] = make_float4(v.x * inv, v.y * inv, v.z * inv, v.w * inv);
        *cell = make_float4(0.f, 0.f, 0.f, 0.f);   // reset for next replay
    }
    __syncthreads();

    // out[b, m, wbase+k] = sum_l mask[b,l,m] * sem[l][k]   (4 outputs/thread)
    #pragma unroll
    for (int i = t; i < Mc * CK; i += NTHR) {
        const int m = i / CK;
        const int k = i % CK;
        float4 acc = make_float4(0.f, 0.f, 0.f, 0.f);
        #pragma unroll
        for (int l = 0; l < Lc; l++) {
            const float mk = s_mask[l * Mc + m];
            float4 sv = s_sem[l][k];
            acc.x += mk * sv.x; acc.y += mk * sv.y;
            acc.z += mk * sv.z; acc.w += mk * sv.w;
        }
        reinterpret_cast<float4*>(out)[((size_t)b * Mc + m) * W4 + wbase + k] = acc;
    }
}

// ---------------------------------------------------------------------------
extern "C" void kernel_launch(void* const* d_in, const int* in_sizes, int n_in,
                              void* d_out, int out_size)
{
    const float* embeds = (const float*)d_in[0];  // [L,P,S,B,W]
    const float* mask   = (const float*)d_in[1];  // [B,L,M]
    const float* w0     = (const float*)d_in[2];  // [1,W]
    const float* b0     = (const float*)d_in[3];  // [1]
    const float* w1     = (const float*)d_in[4];  // [1,S]
    const float* b1     = (const float*)d_in[5];  // [1]
    float* out          = (float*)d_out;          // [B,M,W]

    k1_pass<<<Lc * Pc * Bc, NTHR>>>(embeds, w0, w1, b0, b1);
    k_epi<<<Bc * NCHK, NTHR>>>(mask, out);
}

// round 12
// speedup vs baseline: 1.0101x; 1.0101x over previous
#include <cuda_runtime.h>
#include <math.h>

#define Lc 8
#define Pc 8
#define Sc 128
#define Bc 16
#define Wc 768
#define Mc 64
#define W4   (Wc / 4)            // 192 float4 per W row == NTHR
#define ROW4 ((Bc * Wc) / 4)     // s-stride in float4 = 3072
#define NTHR 192
#define CK   24                  // float4 per epilogue w-chunk (one cell/thread)
#define NCHK (W4 / CK)           // 8 chunks -> 128 epilogue CTAs

// Scratch (allocation-free: __device__ globals, zero-initialized at load)
// g_sem is ACCUMULATED by k1 (atomicAdd) and ZEROED by its unique reader in
// k_epi right after consumption -> "g_sem == 0 at k1 entry" holds for the
// correctness call and every graph replay alike.
__device__ float g_sem[Lc * Bc * Wc];       // [l,b,w] unnormalized sem (384 KB)
__device__ float g_e[Lc * Pc * Bc];         // e_p = exp(sigmoid(score)) per (l,p,b)

// ---------------------------------------------------------------------------
// Kernel 1: streaming pass. 1024 blocks x 192 threads; thread t owns float4
// column t, walks 128 s-rows. After the block reduce it computes
// e = exp(sigmoid(score+bias)) and atomically accumulates e*max into g_sem.
// ---------------------------------------------------------------------------
__global__ __launch_bounds__(NTHR, 8)
void k1_pass(const float* __restrict__ embeds,
             const float* __restrict__ w0,
             const float* __restrict__ w1,
             const float* __restrict__ b0,
             const float* __restrict__ b1)
{
    __shared__ float sw1[Sc];
    __shared__ float sred[6];
    __shared__ float s_e;

    const int t = threadIdx.x;             // 0..191
    if (t < Sc) sw1[t] = __ldg(w1 + t);
    __syncthreads();

    const int lpb = blockIdx.x;            // (l*P + p)*B + b
    const int b   = lpb & (Bc - 1);
    const int lp  = lpb >> 4;              // l*8 + p
    const int l   = lp >> 3;

    const float4* base = reinterpret_cast<const float4*>(embeds)
                       + (size_t)lp * Sc * ROW4 + (size_t)b * W4 + t;
    const float4 w0v = __ldg(reinterpret_cast<const float4*>(w0) + t);

    float4 mx = make_float4(-3.4e38f, -3.4e38f, -3.4e38f, -3.4e38f);
    float dot = 0.0f;

    #pragma unroll 4
    for (int s = 0; s < Sc; s++) {
        float4 v = __ldcs(base + (size_t)s * ROW4);   // streaming (evict-first)
        mx.x = fmaxf(mx.x, v.x);
        mx.y = fmaxf(mx.y, v.y);
        mx.z = fmaxf(mx.z, v.z);
        mx.w = fmaxf(mx.w, v.w);
        dot += (v.x * w0v.x + v.y * w0v.y + v.z * w0v.z + v.w * w0v.w) * sw1[s];
    }

    // block-reduce dot
    #pragma unroll
    for (int o = 16; o > 0; o >>= 1)
        dot += __shfl_down_sync(0xffffffffu, dot, o);
    if ((t & 31) == 0) sred[t >> 5] = dot;
    __syncthreads();

    // warp 0: parallel bias sum + final combine (replaces 128-add serial chain)
    if (t < 32) {
        float sw = sw1[t] + sw1[t + 32] + sw1[t + 64] + sw1[t + 96];
        #pragma unroll
        for (int o = 16; o > 0; o >>= 1)
            sw += __shfl_down_sync(0xffffffffu, sw, o);
        if (t == 0) {
            float score = sred[0] + sred[1] + sred[2] + sred[3] + sred[4] + sred[5]
                        + b0[0] * sw + b1[0];
            float sig = 1.0f / (1.0f + __expf(-score));   // sigmoid in (0,1)
            float e   = __expf(sig);                      // unnormalized softmax wt
            g_e[lpb] = e;                                 // plain store (overwritten)
            s_e = e;
        }
    }
    __syncthreads();

    // accumulate e * max into sem[l,b,w] (4 coalesced REDG.F32 per thread)
    const float e = s_e;
    float* semp = g_sem + ((size_t)l * Bc + b) * Wc + 4 * t;
    atomicAdd(semp + 0, e * mx.x);
    atomicAdd(semp + 1, e * mx.y);
    atomicAdd(semp + 2, e * mx.z);
    atomicAdd(semp + 3, e * mx.w);
}

// ---------------------------------------------------------------------------
// Kernel 2: epilogue, load-first. 128 CTAs = (b, w-chunk of 24 float4).
// Thread t owns ONE sem cell (l = t/24, k = t%24), loaded at instruction 0.
// Normalization is folded into the mask (invE per l), so the sem path has
// no dependency on the e path. Cells are zeroed after reading (replay reset).
// Out stage: 1536 float4 per CTA, 8 per thread, all smem FMAs.
// ---------------------------------------------------------------------------
__global__ __launch_bounds__(NTHR)
void k_epi(const float* __restrict__ mask,
           float* __restrict__ out)
{
    __shared__ float  s_mask[Lc * Mc];       // 512 floats = mask[b,:,:]
    __shared__ float  s_e[Lc * Pc];
    __shared__ float  s_inv[Lc];
    __shared__ float4 s_sem[Lc][CK];         // 3 KB

    const int t     = threadIdx.x;           // 0..191
    const int b     = blockIdx.x >> 3;
    const int chunk = blockIdx.x & (NCHK - 1);
    const int wbase = chunk * CK;             // float4 offset within W4

    const int l = t / CK;                     // 0..7
    const int k = t % CK;                     // 0..23

    // ---- instr 0: fire all independent global loads ----------------------
    float4* cell = reinterpret_cast<float4*>(
        g_sem + ((size_t)l * Bc + b) * Wc) + wbase + k;
    float4 v = __ldcg(cell);                                  // own sem cell

    if (t < Lc * Pc)
        s_e[t] = __ldcg(g_e + t * Bc + b);                    // e values

    #pragma unroll
    for (int i = t; i < Lc * Mc; i += NTHR)                   // mask[b,:,:]
        s_mask[i] = __ldg(mask + (size_t)b * Lc * Mc + i);

    // ---- stash cell, reset global, publish inv ---------------------------
    s_sem[l][k] = v;
    *cell = make_float4(0.f, 0.f, 0.f, 0.f);   // reset for next replay
    __syncthreads();

    if (t < Lc) {
        float s = 0.0f;
        #pragma unroll
        for (int p = 0; p < Pc; p++) s += s_e[t * Pc + p];
        s_inv[t] = 1.0f / s;
    }
    __syncthreads();

    // ---- out[b, m, wbase+k] = sum_l (mask*inv) * semraw -------------------
    #pragma unroll
    for (int j = 0; j < (Mc * CK) / NTHR; j++) {               // 8 outputs
        const int i  = t + j * NTHR;
        const int m  = i / CK;
        const int kk = i % CK;
        float4 acc = make_float4(0.f, 0.f, 0.f, 0.f);
        #pragma unroll
        for (int ll = 0; ll < Lc; ll++) {
            const float mk = s_mask[ll * Mc + m] * s_inv[ll];
            float4 sv = s_sem[ll][kk];
            acc.x += mk * sv.x; acc.y += mk * sv.y;
            acc.z += mk * sv.z; acc.w += mk * sv.w;
        }
        reinterpret_cast<float4*>(out)[((size_t)b * Mc + m) * W4 + wbase + kk] = acc;
    }
}

// ---------------------------------------------------------------------------
extern "C" void kernel_launch(void* const* d_in, const int* in_sizes, int n_in,
                              void* d_out, int out_size)
{
    const float* embeds = (const float*)d_in[0];  // [L,P,S,B,W]
    const float* mask   = (const float*)d_in[1];  // [B,L,M]
    const float* w0     = (const float*)d_in[2];  // [1,W]
    const float* b0     = (const float*)d_in[3];  // [1]
    const float* w1     = (const float*)d_in[4];  // [1,S]
    const float* b1     = (const float*)d_in[5];  // [1]
    float* out          = (float*)d_out;          // [B,M,W]

    k1_pass<<<Lc * Pc * Bc, NTHR>>>(embeds, w0, w1, b0, b1);
    k_epi<<<Bc * NCHK, NTHR>>>(mask, out);
}

// round 14
// speedup vs baseline: 1.0242x; 1.0140x over previous
#include <cuda_runtime.h>
#include <math.h>

#define Lc 8
#define Pc 8
#define Sc 128
#define Bc 16
#define Wc 768
#define Mc 64
#define W4   (Wc / 4)            // 192 float4 per W row == NTHR
#define ROW4 ((Bc * Wc) / 4)     // s-stride in float4 = 3072
#define NTHR 192
#define CK   24                  // float4 per epilogue w-chunk (one cell/thread)
#define NCHK (W4 / CK)           // 8 chunks -> 128 epilogue CTAs

// Scratch (allocation-free: __device__ globals, zero-initialized at load)
// g_sem is ACCUMULATED by k1 (atomicAdd) and ZEROED by its unique reader in
// k_epi right after consumption -> "g_sem == 0 at k1 entry" holds for the
// correctness call and every graph replay alike.
__device__ float g_sem[Lc * Bc * Wc];       // [l,b,w] unnormalized sem (384 KB)
__device__ float g_e[Lc * Pc * Bc];         // e_p = exp(sigmoid(score)) per (l,p,b)

// ---------------------------------------------------------------------------
// Kernel 1: streaming pass. 1024 blocks x 192 threads; thread t owns float4
// column t, walks 128 s-rows. After the block reduce it computes
// e = exp(sigmoid(score+bias)) and atomically accumulates e*max into g_sem.
// ---------------------------------------------------------------------------
__global__ __launch_bounds__(NTHR, 8)
void k1_pass(const float* __restrict__ embeds,
             const float* __restrict__ w0,
             const float* __restrict__ w1,
             const float* __restrict__ b0,
             const float* __restrict__ b1)
{
    __shared__ float sw1[Sc];
    __shared__ float sred[6];
    __shared__ float s_e;

    const int t = threadIdx.x;             // 0..191
    if (t < Sc) sw1[t] = __ldg(w1 + t);
    __syncthreads();

    const int lpb = blockIdx.x;            // (l*P + p)*B + b
    const int b   = lpb & (Bc - 1);
    const int lp  = lpb >> 4;              // l*8 + p
    const int l   = lp >> 3;

    const float4* base = reinterpret_cast<const float4*>(embeds)
                       + (size_t)lp * Sc * ROW4 + (size_t)b * W4 + t;
    const float4 w0v = __ldg(reinterpret_cast<const float4*>(w0) + t);

    float4 mx = make_float4(-3.4e38f, -3.4e38f, -3.4e38f, -3.4e38f);
    float dot = 0.0f;

    #pragma unroll 4
    for (int s = 0; s < Sc; s++) {
        float4 v = __ldcs(base + (size_t)s * ROW4);   // streaming (evict-first)
        mx.x = fmaxf(mx.x, v.x);
        mx.y = fmaxf(mx.y, v.y);
        mx.z = fmaxf(mx.z, v.z);
        mx.w = fmaxf(mx.w, v.w);
        dot += (v.x * w0v.x + v.y * w0v.y + v.z * w0v.z + v.w * w0v.w) * sw1[s];
    }

    // block-reduce dot
    #pragma unroll
    for (int o = 16; o > 0; o >>= 1)
        dot += __shfl_down_sync(0xffffffffu, dot, o);
    if ((t & 31) == 0) sred[t >> 5] = dot;
    __syncthreads();

    // warp 0: parallel bias sum + final combine
    if (t < 32) {
        float sw = sw1[t] + sw1[t + 32] + sw1[t + 64] + sw1[t + 96];
        #pragma unroll
        for (int o = 16; o > 0; o >>= 1)
            sw += __shfl_down_sync(0xffffffffu, sw, o);
        if (t == 0) {
            float score = sred[0] + sred[1] + sred[2] + sred[3] + sred[4] + sred[5]
                        + b0[0] * sw + b1[0];
            float sig = 1.0f / (1.0f + __expf(-score));   // sigmoid in (0,1)
            float e   = __expf(sig);                      // unnormalized softmax wt
            g_e[lpb] = e;                                 // plain store (overwritten)
            s_e = e;
        }
    }
    __syncthreads();

    // accumulate e * max into sem[l,b,w] (4 coalesced REDG.F32 per thread)
    const float e = s_e;
    float* semp = g_sem + ((size_t)l * Bc + b) * Wc + 4 * t;
    atomicAdd(semp + 0, e * mx.x);
    atomicAdd(semp + 1, e * mx.y);
    atomicAdd(semp + 2, e * mx.z);
    atomicAdd(semp + 3, e * mx.w);
}

// ---------------------------------------------------------------------------
// Kernel 2: epilogue with PDL overlap. 128 CTAs = (b, w-chunk of 24 float4).
// PRE-SYNC  (overlaps k1's tail): mask[b,:,:] -> smem (input data, k1-free).
// POST-SYNC: one g_sem cell per thread + e loads fire together; normalize is
// folded into mask weights; cells zeroed after read (replay reset).
// ---------------------------------------------------------------------------
__global__ __launch_bounds__(NTHR)
void k_epi(const float* __restrict__ mask,
           float* __restrict__ out)
{
    __shared__ float  s_mask[Lc * Mc];       // 512 floats = mask[b,:,:]
    __shared__ float  s_e[Lc * Pc];
    __shared__ float  s_inv[Lc];
    __shared__ float4 s_sem[Lc][CK];         // 3 KB

    const int t     = threadIdx.x;           // 0..191
    const int b     = blockIdx.x >> 3;
    const int chunk = blockIdx.x & (NCHK - 1);
    const int wbase = chunk * CK;             // float4 offset within W4

    const int l = t / CK;                     // 0..7
    const int k = t % CK;                     // 0..23

    // ---- PRE-SYNC: prologue overlapped with k1 via PDL --------------------
    #pragma unroll
    for (int i = t; i < Lc * Mc; i += NTHR)                   // mask[b,:,:]
        s_mask[i] = __ldg(mask + (size_t)b * Lc * Mc + i);

    float4* cell = reinterpret_cast<float4*>(
        g_sem + ((size_t)l * Bc + b) * Wc) + wbase + k;

    // ---- wait for k1's memory to be visible --------------------------------
    cudaGridDependencySynchronize();

    // ---- POST-SYNC: fire all k1-dependent loads in one window -------------
    float4 v = __ldcg(cell);                                  // own sem cell
    if (t < Lc * Pc)
        s_e[t] = __ldcg(g_e + t * Bc + b);                    // e values

    s_sem[l][k] = v;
    *cell = make_float4(0.f, 0.f, 0.f, 0.f);   // reset for next replay
    __syncthreads();

    if (t < Lc) {
        float s = 0.0f;
        #pragma unroll
        for (int p = 0; p < Pc; p++) s += s_e[t * Pc + p];
        s_inv[t] = 1.0f / s;
    }
    __syncthreads();

    // ---- out[b, m, wbase+k] = sum_l (mask*inv) * semraw --------------------
    #pragma unroll
    for (int j = 0; j < (Mc * CK) / NTHR; j++) {               // 8 outputs
        const int i  = t + j * NTHR;
        const int m  = i / CK;
        const int kk = i % CK;
        float4 acc = make_float4(0.f, 0.f, 0.f, 0.f);
        #pragma unroll
        for (int ll = 0; ll < Lc; ll++) {
            const float mk = s_mask[ll * Mc + m] * s_inv[ll];
            float4 sv = s_sem[ll][kk];
            acc.x += mk * sv.x; acc.y += mk * sv.y;
            acc.z += mk * sv.z; acc.w += mk * sv.w;
        }
        reinterpret_cast<float4*>(out)[((size_t)b * Mc + m) * W4 + wbase + kk] = acc;
    }
}

// ---------------------------------------------------------------------------
extern "C" void kernel_launch(void* const* d_in, const int* in_sizes, int n_in,
                              void* d_out, int out_size)
{
    const float* embeds = (const float*)d_in[0];  // [L,P,S,B,W]
    const float* mask   = (const float*)d_in[1];  // [B,L,M]
    const float* w0     = (const float*)d_in[2];  // [1,W]
    const float* b0     = (const float*)d_in[3];  // [1]
    const float* w1     = (const float*)d_in[4];  // [1,S]
    const float* b1     = (const float*)d_in[5];  // [1]
    float* out          = (float*)d_out;          // [B,M,W]

    k1_pass<<<Lc * Pc * Bc, NTHR>>>(embeds, w0, w1, b0, b1);

    // PDL launch: epi may start while k1 drains; its pre-sync portion
    // (mask -> smem) overlaps k1's tail. Graph-capturable.
    cudaLaunchConfig_t cfg = {};
    cfg.gridDim  = dim3(Bc * NCHK);
    cfg.blockDim = dim3(NTHR);
    cfg.dynamicSmemBytes = 0;
    cfg.stream = 0;                            // legacy default stream (captured)
    cudaLaunchAttribute attrs[1];
    attrs[0].id = cudaLaunchAttributeProgrammaticStreamSerialization;
    attrs[0].val.programmaticStreamSerializationAllowed = 1;
    cfg.attrs = attrs;
    cfg.numAttrs = 1;
    cudaLaunchKernelEx(&cfg, k_epi, mask, (float*)d_out);
}